// round 2
// baseline (speedup 1.0000x reference)
#include <cuda_runtime.h>
#include <math.h>

#define NPTS   8192
#define MPTS   8192
#define NB     16
#define WIDTH  32
#define NSPLIT 19
#define TILE_J 128
#define IBLK   256

// Per-source packed record: x, y, z, wrho, bp[16]  (bp = -beta * log2(e))
__device__ float g_packed[NPTS * 20];
__device__ float g_heg[NB];
__device__ float g_partial[(size_t)NSPLIT * MPTS * NB];

__device__ __forceinline__ float log_coshf_acc(float t) {
    float a = fabsf(t);
    return a + log1pf(expf(-2.0f * a)) - 0.69314718055994531f;
}

// FMA-pipe exp2: magic-number round-to-nearest + degree-5 Taylor on [-0.5, 0.5].
// Integer exponent insert goes to the (idle) alu pipe. Max rel err ~2.4e-6.
__device__ __forceinline__ float exp2_poly(float t) {
    t = fmaxf(t, -126.0f);                       // FMNMX (alu)
    float z = t + 12582912.0f;                   // FADD: round(t) in low mantissa
    int ebits = (__float_as_int(z) + (127 - 0x4B4000)) << 23; // IADD3 + SHF (alu)
    float n = z - 12582912.0f;                   // FADD
    float f = t - n;                             // FADD, f in [-0.5, 0.5]
    float p = 0.00133335581f;
    p = fmaf(p, f, 0.00961812911f);
    p = fmaf(p, f, 0.0555041087f);
    p = fmaf(p, f, 0.240226507f);
    p = fmaf(p, f, 0.69314718056f);
    p = fmaf(p, f, 1.0f);
    return p * __int_as_float(ebits);            // FMUL
}

__global__ void setup_kernel(const float* __restrict__ rho,
                             const float* __restrict__ gamma,
                             const float* __restrict__ coords,
                             const float* __restrict__ weights,
                             const float* __restrict__ w1,
                             const float* __restrict__ b1,
                             const float* __restrict__ w2,
                             const float* __restrict__ b2) {
    int j = blockIdx.x * blockDim.x + threadIdx.x;
    if (j >= NPTS) return;

    // 4 * (3*pi^2)^(2/3) — compile-time constant, NO fp64 at runtime
    const float C = 38.283120002509214f;

    float r = rho[j];
    float s2 = gamma[j] / (C * powf(r, 8.0f / 3.0f));
    float x = logf(s2 + 1e-4f);

    // MLP: 1 -> 32 (tanh) -> 16
    float h[WIDTH];
#pragma unroll
    for (int k = 0; k < WIDTH; k++) h[k] = tanhf(x * w1[k] + b1[k]);

    float pref = 3.14159265358979323846f * powf(0.5f * r, 2.0f / 3.0f);

#pragma unroll
    for (int b = 0; b < NB; b++) {
        float o = b2[b];
#pragma unroll
        for (int k = 0; k < WIDTH; k++) o = fmaf(h[k], w2[k * NB + b], o);
        float lc = log_coshf_acc(o);
        // fold log2(e) so inner loop uses raw ex2 / exp2_poly
        g_packed[j * 20 + 4 + b] = -pref * lc * 1.44269504088896340f;
    }
    g_packed[j * 20 + 0] = coords[j * 3 + 0];
    g_packed[j * 20 + 1] = coords[j * 3 + 1];
    g_packed[j * 20 + 2] = coords[j * 3 + 2];
    g_packed[j * 20 + 3] = weights[j] * r;

    if (j == 0) {
        // heg_scale: field_embed at x = 0
        float h0[WIDTH];
#pragma unroll
        for (int k = 0; k < WIDTH; k++) h0[k] = tanhf(b1[k]);
#pragma unroll
        for (int b = 0; b < NB; b++) {
            float o = b2[b];
#pragma unroll
            for (int k = 0; k < WIDTH; k++) o = fmaf(h0[k], w2[k * NB + b], o);
            float lc = log_coshf_acc(o);
            g_heg[b] = powf(lc, 1.5f);
        }
    }
}

__global__ void __launch_bounds__(IBLK)
main_kernel(const float* __restrict__ out_coords) {
    __shared__ float tile[TILE_J * 20];

    int i = blockIdx.x * IBLK + threadIdx.x;
    int split = blockIdx.y;

    float ox = out_coords[i * 3 + 0];
    float oy = out_coords[i * 3 + 1];
    float oz = out_coords[i * 3 + 2];

    float acc[NB];
#pragma unroll
    for (int b = 0; b < NB; b++) acc[b] = 0.0f;

    int jbeg = (split * NPTS) / NSPLIT;
    int jend = ((split + 1) * NPTS) / NSPLIT;

    for (int t = jbeg; t < jend; t += TILE_J) {
        int cnt = min(TILE_J, jend - t);
        __syncthreads();
        {
            const float4* src = (const float4*)(g_packed + (size_t)t * 20);
            float4* dst = (float4*)tile;
            int nvec = cnt * 5;  // 20 floats = 5 float4 per j
            for (int v = threadIdx.x; v < nvec; v += IBLK) dst[v] = src[v];
        }
        __syncthreads();

        for (int jt = 0; jt < cnt; ++jt) {
            const float* p = tile + jt * 20;
            float4 cw  = *(const float4*)(p);       // x, y, z, wrho
            float4 bp0 = *(const float4*)(p + 4);
            float4 bp1 = *(const float4*)(p + 8);
            float4 bp2 = *(const float4*)(p + 12);
            float4 bp3 = *(const float4*)(p + 16);

            float dx = ox - cw.x;
            float dy = oy - cw.y;
            float dz = oz - cw.z;
            float d2 = fmaf(dx, dx, fmaf(dy, dy, dz * dz));
            float w = cw.w;

            float e[NB];
            // channels 0,1: FMA-pipe polynomial (uses MUFU headroom)
            e[0] = exp2_poly(bp0.x * d2);
            e[1] = exp2_poly(bp0.y * d2);
            // channels 2..15: MUFU ex2
            asm("ex2.approx.f32 %0, %1;" : "=f"(e[2])  : "f"(bp0.z * d2));
            asm("ex2.approx.f32 %0, %1;" : "=f"(e[3])  : "f"(bp0.w * d2));
            asm("ex2.approx.f32 %0, %1;" : "=f"(e[4])  : "f"(bp1.x * d2));
            asm("ex2.approx.f32 %0, %1;" : "=f"(e[5])  : "f"(bp1.y * d2));
            asm("ex2.approx.f32 %0, %1;" : "=f"(e[6])  : "f"(bp1.z * d2));
            asm("ex2.approx.f32 %0, %1;" : "=f"(e[7])  : "f"(bp1.w * d2));
            asm("ex2.approx.f32 %0, %1;" : "=f"(e[8])  : "f"(bp2.x * d2));
            asm("ex2.approx.f32 %0, %1;" : "=f"(e[9])  : "f"(bp2.y * d2));
            asm("ex2.approx.f32 %0, %1;" : "=f"(e[10]) : "f"(bp2.z * d2));
            asm("ex2.approx.f32 %0, %1;" : "=f"(e[11]) : "f"(bp2.w * d2));
            asm("ex2.approx.f32 %0, %1;" : "=f"(e[12]) : "f"(bp3.x * d2));
            asm("ex2.approx.f32 %0, %1;" : "=f"(e[13]) : "f"(bp3.y * d2));
            asm("ex2.approx.f32 %0, %1;" : "=f"(e[14]) : "f"(bp3.z * d2));
            asm("ex2.approx.f32 %0, %1;" : "=f"(e[15]) : "f"(bp3.w * d2));

#pragma unroll
            for (int b = 0; b < NB; b++) acc[b] = fmaf(e[b], w, acc[b]);
        }
    }

    float* outp = g_partial + ((size_t)split * MPTS + i) * NB;
#pragma unroll
    for (int b = 0; b < NB; b++) outp[b] = acc[b];
}

__global__ void reduce_kernel(float* __restrict__ out) {
    int idx = blockIdx.x * blockDim.x + threadIdx.x;  // i*NB + b
    if (idx >= MPTS * NB) return;
    int b = idx & (NB - 1);
    float s = 0.0f;
#pragma unroll
    for (int sp = 0; sp < NSPLIT; sp++)
        s += g_partial[(size_t)sp * (MPTS * NB) + idx];
    out[idx] = s * g_heg[b];
}

extern "C" void kernel_launch(void* const* d_in, const int* in_sizes, int n_in,
                              void* d_out, int out_size) {
    const float* rho        = (const float*)d_in[0];
    const float* gamma      = (const float*)d_in[1];
    const float* coords     = (const float*)d_in[2];
    const float* weights    = (const float*)d_in[3];
    const float* out_coords = (const float*)d_in[4];
    const float* w1         = (const float*)d_in[5];
    const float* b1         = (const float*)d_in[6];
    const float* w2         = (const float*)d_in[7];
    const float* b2         = (const float*)d_in[8];
    float* out = (float*)d_out;

    setup_kernel<<<(NPTS + 255) / 256, 256>>>(rho, gamma, coords, weights,
                                              w1, b1, w2, b2);
    dim3 grid(MPTS / IBLK, NSPLIT);
    main_kernel<<<grid, IBLK>>>(out_coords);
    reduce_kernel<<<(MPTS * NB + 255) / 256, 256>>>(out);
}

// round 3
// speedup vs baseline: 1.1371x; 1.1371x over previous
#include <cuda_runtime.h>
#include <math.h>

#define NPTS   8192
#define MPTS   8192
#define NB     16
#define WIDTH  32
#define NSPLIT 19
#define TILE_J 128
#define IBLK   256

// Per-source packed record: x, y, z, wrho, bp[16]  (bp = -beta * log2(e))
__device__ float g_packed[NPTS * 20];
__device__ float g_heg[NB];
__device__ float g_partial[(size_t)NSPLIT * MPTS * NB];

__device__ __forceinline__ float log_coshf_acc(float t) {
    float a = fabsf(t);
    return a + log1pf(expf(-2.0f * a)) - 0.69314718055994531f;
}

__global__ void setup_kernel(const float* __restrict__ rho,
                             const float* __restrict__ gamma,
                             const float* __restrict__ coords,
                             const float* __restrict__ weights,
                             const float* __restrict__ w1,
                             const float* __restrict__ b1,
                             const float* __restrict__ w2,
                             const float* __restrict__ b2) {
    int j = blockIdx.x * blockDim.x + threadIdx.x;
    if (j >= NPTS) return;

    // 4 * (3*pi^2)^(2/3) — compile-time constant, no fp64 at runtime
    const float C = 38.283120002509214f;

    float r = rho[j];
    float s2 = gamma[j] / (C * powf(r, 8.0f / 3.0f));
    float x = logf(s2 + 1e-4f);

    // MLP: 1 -> 32 (tanh) -> 16
    float h[WIDTH];
#pragma unroll
    for (int k = 0; k < WIDTH; k++) h[k] = tanhf(x * w1[k] + b1[k]);

    float pref = 3.14159265358979323846f * powf(0.5f * r, 2.0f / 3.0f);

#pragma unroll
    for (int b = 0; b < NB; b++) {
        float o = b2[b];
#pragma unroll
        for (int k = 0; k < WIDTH; k++) o = fmaf(h[k], w2[k * NB + b], o);
        float lc = log_coshf_acc(o);
        // fold log2(e) so inner loop uses raw ex2
        g_packed[j * 20 + 4 + b] = -pref * lc * 1.44269504088896340f;
    }
    g_packed[j * 20 + 0] = coords[j * 3 + 0];
    g_packed[j * 20 + 1] = coords[j * 3 + 1];
    g_packed[j * 20 + 2] = coords[j * 3 + 2];
    g_packed[j * 20 + 3] = weights[j] * r;

    if (j == 0) {
        // heg_scale: field_embed at x = 0
        float h0[WIDTH];
#pragma unroll
        for (int k = 0; k < WIDTH; k++) h0[k] = tanhf(b1[k]);
#pragma unroll
        for (int b = 0; b < NB; b++) {
            float o = b2[b];
#pragma unroll
            for (int k = 0; k < WIDTH; k++) o = fmaf(h0[k], w2[k * NB + b], o);
            float lc = log_coshf_acc(o);
            g_heg[b] = powf(lc, 1.5f);
        }
    }
}

__global__ void __launch_bounds__(IBLK)
main_kernel(const float* __restrict__ out_coords) {
    __shared__ float tile[TILE_J * 20];

    int i = blockIdx.x * IBLK + threadIdx.x;
    int split = blockIdx.y;

    float ox = out_coords[i * 3 + 0];
    float oy = out_coords[i * 3 + 1];
    float oz = out_coords[i * 3 + 2];

    float acc[NB];
#pragma unroll
    for (int b = 0; b < NB; b++) acc[b] = 0.0f;

    int jbeg = (split * NPTS) / NSPLIT;
    int jend = ((split + 1) * NPTS) / NSPLIT;

    for (int t = jbeg; t < jend; t += TILE_J) {
        int cnt = min(TILE_J, jend - t);
        __syncthreads();
        {
            const float4* src = (const float4*)(g_packed + (size_t)t * 20);
            float4* dst = (float4*)tile;
            int nvec = cnt * 5;  // 20 floats = 5 float4 per j
            for (int v = threadIdx.x; v < nvec; v += IBLK) dst[v] = src[v];
        }
        __syncthreads();

        for (int jt = 0; jt < cnt; ++jt) {
            const float* p = tile + jt * 20;
            float4 cw = *(const float4*)p;  // x, y, z, wrho
            float dx = ox - cw.x;
            float dy = oy - cw.y;
            float dz = oz - cw.z;
            float d2 = fmaf(dx, dx, fmaf(dy, dy, dz * dz));
            float w = cw.w;
#pragma unroll
            for (int b = 0; b < NB; b++) {
                float e;
                float arg = p[4 + b] * d2;  // -beta*log2e*d2
                asm("ex2.approx.f32 %0, %1;" : "=f"(e) : "f"(arg));
                acc[b] = fmaf(e, w, acc[b]);
            }
        }
    }

    float* outp = g_partial + ((size_t)split * MPTS + i) * NB;
#pragma unroll
    for (int b = 0; b < NB; b++) outp[b] = acc[b];
}

__global__ void reduce_kernel(float* __restrict__ out) {
    int idx = blockIdx.x * blockDim.x + threadIdx.x;  // i*NB + b
    if (idx >= MPTS * NB) return;
    int b = idx & (NB - 1);
    float s = 0.0f;
#pragma unroll
    for (int sp = 0; sp < NSPLIT; sp++)
        s += g_partial[(size_t)sp * (MPTS * NB) + idx];
    out[idx] = s * g_heg[b];
}

extern "C" void kernel_launch(void* const* d_in, const int* in_sizes, int n_in,
                              void* d_out, int out_size) {
    const float* rho        = (const float*)d_in[0];
    const float* gamma      = (const float*)d_in[1];
    const float* coords     = (const float*)d_in[2];
    const float* weights    = (const float*)d_in[3];
    const float* out_coords = (const float*)d_in[4];
    const float* w1         = (const float*)d_in[5];
    const float* b1         = (const float*)d_in[6];
    const float* w2         = (const float*)d_in[7];
    const float* b2         = (const float*)d_in[8];
    float* out = (float*)d_out;

    // 64-thread blocks -> 128 blocks: spread the latency-bound per-point MLP
    // work across all SMs instead of 32.
    setup_kernel<<<NPTS / 64, 64>>>(rho, gamma, coords, weights,
                                    w1, b1, w2, b2);
    dim3 grid(MPTS / IBLK, NSPLIT);
    main_kernel<<<grid, IBLK>>>(out_coords);
    reduce_kernel<<<(MPTS * NB + 255) / 256, 256>>>(out);
}

// round 4
// speedup vs baseline: 1.1695x; 1.0285x over previous
#include <cuda_runtime.h>
#include <math.h>

#define NPTS   8192
#define MPTS   8192
#define NB     16
#define WIDTH  32
#define NSPLIT 19
#define TILE_J 128
#define IBLK   256

// Per-source packed record: x, y, z, wrho, bp[16]  (bp = -beta * log2(e))
__device__ float g_packed[NPTS * 20];
__device__ float g_heg[NB];
__device__ float g_partial[(size_t)NSPLIT * MPTS * NB];

__device__ __forceinline__ float log_coshf_acc(float t) {
    float a = fabsf(t);
    return a + log1pf(expf(-2.0f * a)) - 0.69314718055994531f;
}

// Warp-per-point setup: lane k owns hidden unit k (one tanhf each);
// the WIDTH->NB layer is done with 32 SHFL.IDX broadcasts; lane b<16
// owns output basis b (one log_cosh each).
__global__ void __launch_bounds__(256)
setup_kernel(const float* __restrict__ rho,
             const float* __restrict__ gamma,
             const float* __restrict__ coords,
             const float* __restrict__ weights,
             const float* __restrict__ w1,
             const float* __restrict__ b1,
             const float* __restrict__ w2,
             const float* __restrict__ b2) {
    __shared__ float s_w2[WIDTH * NB];
    int tid = threadIdx.x;
    for (int v = tid; v < WIDTH * NB; v += blockDim.x) s_w2[v] = w2[v];
    __syncthreads();

    int lane = tid & 31;
    int warp = tid >> 5;
    int j = blockIdx.x * (blockDim.x >> 5) + warp;
    if (j >= NPTS) return;

    const float C = 38.283120002509214f;   // 4*(3*pi^2)^(2/3)
    const float LOG2E = 1.44269504088896340f;

    float r = rho[j];
    float s2 = gamma[j] / (C * powf(r, 8.0f / 3.0f));
    float x = logf(s2 + 1e-4f);

    // hidden layer: one tanh per lane
    float h = tanhf(fmaf(x, w1[lane], b1[lane]));

    // output layer: lane b (b<16) accumulates o_b
    int bl = lane & (NB - 1);
    float o = b2[bl];
#pragma unroll
    for (int k = 0; k < WIDTH; k++) {
        float hk = __shfl_sync(0xffffffffu, h, k);
        o = fmaf(hk, s_w2[k * NB + bl], o);
    }

    float pref = 3.14159265358979323846f * powf(0.5f * r, 2.0f / 3.0f);
    float lc = log_coshf_acc(o);
    float bp = -pref * lc * LOG2E;

    if (lane < NB) g_packed[j * 20 + 4 + lane] = bp;
    if (lane == 16) g_packed[j * 20 + 0] = coords[j * 3 + 0];
    if (lane == 17) g_packed[j * 20 + 1] = coords[j * 3 + 1];
    if (lane == 18) g_packed[j * 20 + 2] = coords[j * 3 + 2];
    if (lane == 19) g_packed[j * 20 + 3] = weights[j] * r;

    if (j == 0) {
        // heg_scale: field_embed at x = 0, same warp-parallel path
        float h0 = tanhf(b1[lane]);
        float o0 = b2[bl];
#pragma unroll
        for (int k = 0; k < WIDTH; k++) {
            float hk = __shfl_sync(0xffffffffu, h0, k);
            o0 = fmaf(hk, s_w2[k * NB + bl], o0);
        }
        if (lane < NB) g_heg[lane] = powf(log_coshf_acc(o0), 1.5f);
    }
}

__global__ void __launch_bounds__(IBLK)
main_kernel(const float* __restrict__ out_coords) {
    __shared__ float tile[TILE_J * 20];

    int i = blockIdx.x * IBLK + threadIdx.x;
    int split = blockIdx.y;

    float ox = out_coords[i * 3 + 0];
    float oy = out_coords[i * 3 + 1];
    float oz = out_coords[i * 3 + 2];

    float acc[NB];
#pragma unroll
    for (int b = 0; b < NB; b++) acc[b] = 0.0f;

    int jbeg = (split * NPTS) / NSPLIT;
    int jend = ((split + 1) * NPTS) / NSPLIT;

    for (int t = jbeg; t < jend; t += TILE_J) {
        int cnt = min(TILE_J, jend - t);
        __syncthreads();
        {
            const float4* src = (const float4*)(g_packed + (size_t)t * 20);
            float4* dst = (float4*)tile;
            int nvec = cnt * 5;  // 20 floats = 5 float4 per j
            for (int v = threadIdx.x; v < nvec; v += IBLK) dst[v] = src[v];
        }
        __syncthreads();

        for (int jt = 0; jt < cnt; ++jt) {
            const float* p = tile + jt * 20;
            float4 cw = *(const float4*)p;  // x, y, z, wrho
            float dx = ox - cw.x;
            float dy = oy - cw.y;
            float dz = oz - cw.z;
            float d2 = fmaf(dx, dx, fmaf(dy, dy, dz * dz));
            float w = cw.w;
#pragma unroll
            for (int b = 0; b < NB; b++) {
                float e;
                float arg = p[4 + b] * d2;  // -beta*log2e*d2
                asm("ex2.approx.f32 %0, %1;" : "=f"(e) : "f"(arg));
                acc[b] = fmaf(e, w, acc[b]);
            }
        }
    }

    float* outp = g_partial + ((size_t)split * MPTS + i) * NB;
#pragma unroll
    for (int b = 0; b < NB; b++) outp[b] = acc[b];
}

__global__ void reduce_kernel(float* __restrict__ out) {
    int idx = blockIdx.x * blockDim.x + threadIdx.x;  // i*NB + b
    if (idx >= MPTS * NB) return;
    int b = idx & (NB - 1);
    float s = 0.0f;
#pragma unroll
    for (int sp = 0; sp < NSPLIT; sp++)
        s += g_partial[(size_t)sp * (MPTS * NB) + idx];
    out[idx] = s * g_heg[b];
}

extern "C" void kernel_launch(void* const* d_in, const int* in_sizes, int n_in,
                              void* d_out, int out_size) {
    const float* rho        = (const float*)d_in[0];
    const float* gamma      = (const float*)d_in[1];
    const float* coords     = (const float*)d_in[2];
    const float* weights    = (const float*)d_in[3];
    const float* out_coords = (const float*)d_in[4];
    const float* w1         = (const float*)d_in[5];
    const float* b1         = (const float*)d_in[6];
    const float* w2         = (const float*)d_in[7];
    const float* b2         = (const float*)d_in[8];
    float* out = (float*)d_out;

    // warp-per-point: 8 warps/block -> 1024 blocks
    setup_kernel<<<NPTS / 8, 256>>>(rho, gamma, coords, weights,
                                    w1, b1, w2, b2);
    dim3 grid(MPTS / IBLK, NSPLIT);
    main_kernel<<<grid, IBLK>>>(out_coords);
    reduce_kernel<<<(MPTS * NB + 255) / 256, 256>>>(out);
}